// round 10
// baseline (speedup 1.0000x reference)
#include <cuda_runtime.h>
#include <cstdint>

// Triangle_39719857553609 — FINAL (confirmed R8/R9, session best).
//   in : decompFE [32768, 2016] f32 (flat strict-lower-triangle, tril(-1) order)
//   out: [32768, 64, 64] f32, symmetric, zero diagonal.
//
// One CTA per matrix, 256 threads, 24.4 KB smem (8 CTAs/SM):
//   cp.async.bulk G->S (8064 B row, mbarrier)
//   -> build rows 0..31 -> bulk store 8 KB (store engine starts early)
//   -> build rows 32..63 -> bulk store 8 KB.
//
// ROOFLINE EVIDENCE (9 benches, 8 structural variants):
//   traffic: 264 MB read + 537 MB write (irreducible — dense symmetric output
//            mandated by reference; d_out poisoned so every byte written).
//   plateau: 6.4-6.5 TB/s (80-82% HBM spec) regardless of access path
//            (LDG/STG, .cs hints, UBLKCP both ways, burst splitting),
//            occupancy >= 8 CTA/SM, or pipelining. Persistence and fat CTAs
//            regress (fewer independent streams). Matches B300_MICROARCH
//            path-independent LTS throughput cap.
//   this config: bench 119.2 us, ncu 113.9 us, DRAM 82.2% — machine ceiling.

#define NC2        2016
#define ROW_BYTES  (NC2 * 4)            // 8064
#define N_ATOMS    64
#define MAT        (N_ATOMS * N_ATOMS)  // 4096
#define HALF       (MAT / 2)            // 2048 floats = 8192 B
#define HALF_BYTES (HALF * 4)
#define THREADS    256

__device__ __forceinline__ uint32_t smem_u32(const void* p) {
    uint32_t a;
    asm("{ .reg .u64 t; cvta.to.shared.u64 t, %1; cvt.u32.u64 %0, t; }"
        : "=r"(a) : "l"(p));
    return a;
}

__device__ __forceinline__ void build_half(const float* __restrict__ s_row,
                                           float4* __restrict__ m4,
                                           int tid, int row_base)
{
    // 512 float4 per half: 2 per thread
    #pragma unroll
    for (int q = 0; q < HALF / 4 / THREADS; q++) {
        const int e4 = tid + q * THREADS;            // float4 idx within half
        const int i  = row_base + (e4 >> 4);         // global row
        const int j0 = (e4 & 15) << 2;
        const int tri_i = (i * (i - 1)) >> 1;

        float4 v;
        float* vp = reinterpret_cast<float*>(&v);
        #pragma unroll
        for (int mI = 0; mI < 4; mI++) {
            const int j = j0 + mI;
            float val;
            if (j < i)       val = s_row[tri_i + j];                 // lower
            else if (j > i)  val = s_row[((j * (j - 1)) >> 1) + i];  // upper
            else             val = 0.0f;                             // diag
            vp[mI] = val;
        }
        m4[e4] = v;
    }
}

__global__ __launch_bounds__(THREADS) void triangle_kernel(
    const float* __restrict__ in, float* __restrict__ out)
{
    __shared__ alignas(16) float s_row[NC2];
    __shared__ alignas(16) float s_mat[MAT];
    __shared__ alignas(8)  uint64_t s_mbar;

    const int tid = threadIdx.x;
    const size_t b = blockIdx.x;

    const uint32_t mbar_a = smem_u32(&s_mbar);

    // ---- init mbarrier, single bulk load of the input row ----
    if (tid == 0) {
        asm volatile("mbarrier.init.shared.b64 [%0], 1;" :: "r"(mbar_a) : "memory");
        asm volatile("fence.proxy.async.shared::cta;" ::: "memory");
        asm volatile("mbarrier.arrive.expect_tx.shared.b64 _, [%0], %1;"
                     :: "r"(mbar_a), "r"((uint32_t)ROW_BYTES) : "memory");
        asm volatile(
            "cp.async.bulk.shared::cta.global.mbarrier::complete_tx::bytes "
            "[%0], [%1], %2, [%3];"
            :: "r"(smem_u32(s_row)), "l"(in + b * NC2),
               "r"((uint32_t)ROW_BYTES), "r"(mbar_a) : "memory");
    }
    __syncthreads();

    // all threads wait for the row (parity 0)
    asm volatile(
        "{\n\t"
        ".reg .pred p;\n\t"
        "W_%=:\n\t"
        "mbarrier.try_wait.parity.shared.b64 p, [%0], 0;\n\t"
        "@!p bra W_%=;\n\t"
        "}"
        :: "r"(mbar_a) : "memory");

    // ---- first half: rows 0..31, store 8 KB early ----
    build_half(s_row, reinterpret_cast<float4*>(s_mat), tid, 0);
    __syncthreads();
    if (tid == 0) {
        asm volatile("fence.proxy.async.shared::cta;" ::: "memory");
        asm volatile(
            "cp.async.bulk.global.shared::cta.bulk_group [%0], [%1], %2;"
            :: "l"(out + b * MAT), "r"(smem_u32(s_mat)),
               "r"((uint32_t)HALF_BYTES) : "memory");
        asm volatile("cp.async.bulk.commit_group;" ::: "memory");
    }

    // ---- second half: rows 32..63 ----
    build_half(s_row, reinterpret_cast<float4*>(s_mat + HALF), tid, 32);
    __syncthreads();
    if (tid == 0) {
        asm volatile("fence.proxy.async.shared::cta;" ::: "memory");
        asm volatile(
            "cp.async.bulk.global.shared::cta.bulk_group [%0], [%1], %2;"
            :: "l"(out + b * MAT + HALF), "r"(smem_u32(s_mat + HALF)),
               "r"((uint32_t)HALF_BYTES) : "memory");
        asm volatile("cp.async.bulk.commit_group;" ::: "memory");
        asm volatile("cp.async.bulk.wait_group 0;" ::: "memory");
    }
}

extern "C" void kernel_launch(void* const* d_in, const int* in_sizes, int n_in,
                              void* d_out, int out_size)
{
    const float* decompFE = (const float*)d_in[0];
    float* out = (float*)d_out;

    const int batch = in_sizes[0] / NC2;   // 32768
    triangle_kernel<<<batch, THREADS>>>(decompFE, out);
}

// round 11
// speedup vs baseline: 1.0057x; 1.0057x over previous
#include <cuda_runtime.h>
#include <cstdint>

// Triangle_39719857553609 — FINAL (session best, confirmed R8/R9/R10).
//   in : decompFE [32768, 2016] f32 (flat strict-lower-triangle, tril(-1) order)
//   out: [32768, 64, 64] f32, symmetric, zero diagonal.
//
// One CTA per matrix, 256 threads, 24.4 KB smem (8 CTAs/SM):
//   cp.async.bulk G->S (8064 B row, mbarrier)
//   -> build rows 0..31 -> bulk store 8 KB (store engine starts early)
//   -> build rows 32..63 -> bulk store 8 KB.
//
// ROOFLINE EVIDENCE (10 benches, 8 structural variants):
//   traffic: 264 MB read + 537 MB write (irreducible — dense symmetric output
//            mandated by reference; d_out poisoned so every byte written).
//   plateau: 6.4-6.5 TB/s (80-82% HBM spec) invariant across access path
//            (LDG/STG, .cs hints, UBLKCP both ways, burst sizes 16B-32KB),
//            occupancy 8-16 CTA/SM, pipelining, split epilogues. Persistence
//            and fat CTAs regress (fewer independent streams). Matches
//            B300_MICROARCH path-independent LTS throughput cap.
//   this config: bench 119.2-119.6 us (4 runs), ncu 113.9-114.2 us,
//   DRAM 82.0-82.2% — machine ceiling for this 1:2 R/W streaming mix.

#define NC2        2016
#define ROW_BYTES  (NC2 * 4)            // 8064
#define N_ATOMS    64
#define MAT        (N_ATOMS * N_ATOMS)  // 4096
#define HALF       (MAT / 2)            // 2048 floats = 8192 B
#define HALF_BYTES (HALF * 4)
#define THREADS    256

__device__ __forceinline__ uint32_t smem_u32(const void* p) {
    uint32_t a;
    asm("{ .reg .u64 t; cvta.to.shared.u64 t, %1; cvt.u32.u64 %0, t; }"
        : "=r"(a) : "l"(p));
    return a;
}

__device__ __forceinline__ void build_half(const float* __restrict__ s_row,
                                           float4* __restrict__ m4,
                                           int tid, int row_base)
{
    // 512 float4 per half: 2 per thread
    #pragma unroll
    for (int q = 0; q < HALF / 4 / THREADS; q++) {
        const int e4 = tid + q * THREADS;            // float4 idx within half
        const int i  = row_base + (e4 >> 4);         // global row
        const int j0 = (e4 & 15) << 2;
        const int tri_i = (i * (i - 1)) >> 1;

        float4 v;
        float* vp = reinterpret_cast<float*>(&v);
        #pragma unroll
        for (int mI = 0; mI < 4; mI++) {
            const int j = j0 + mI;
            float val;
            if (j < i)       val = s_row[tri_i + j];                 // lower
            else if (j > i)  val = s_row[((j * (j - 1)) >> 1) + i];  // upper
            else             val = 0.0f;                             // diag
            vp[mI] = val;
        }
        m4[e4] = v;
    }
}

__global__ __launch_bounds__(THREADS) void triangle_kernel(
    const float* __restrict__ in, float* __restrict__ out)
{
    __shared__ alignas(16) float s_row[NC2];
    __shared__ alignas(16) float s_mat[MAT];
    __shared__ alignas(8)  uint64_t s_mbar;

    const int tid = threadIdx.x;
    const size_t b = blockIdx.x;

    const uint32_t mbar_a = smem_u32(&s_mbar);

    // ---- init mbarrier, single bulk load of the input row ----
    if (tid == 0) {
        asm volatile("mbarrier.init.shared.b64 [%0], 1;" :: "r"(mbar_a) : "memory");
        asm volatile("fence.proxy.async.shared::cta;" ::: "memory");
        asm volatile("mbarrier.arrive.expect_tx.shared.b64 _, [%0], %1;"
                     :: "r"(mbar_a), "r"((uint32_t)ROW_BYTES) : "memory");
        asm volatile(
            "cp.async.bulk.shared::cta.global.mbarrier::complete_tx::bytes "
            "[%0], [%1], %2, [%3];"
            :: "r"(smem_u32(s_row)), "l"(in + b * NC2),
               "r"((uint32_t)ROW_BYTES), "r"(mbar_a) : "memory");
    }
    __syncthreads();

    // all threads wait for the row (parity 0)
    asm volatile(
        "{\n\t"
        ".reg .pred p;\n\t"
        "W_%=:\n\t"
        "mbarrier.try_wait.parity.shared.b64 p, [%0], 0;\n\t"
        "@!p bra W_%=;\n\t"
        "}"
        :: "r"(mbar_a) : "memory");

    // ---- first half: rows 0..31, store 8 KB early ----
    build_half(s_row, reinterpret_cast<float4*>(s_mat), tid, 0);
    __syncthreads();
    if (tid == 0) {
        asm volatile("fence.proxy.async.shared::cta;" ::: "memory");
        asm volatile(
            "cp.async.bulk.global.shared::cta.bulk_group [%0], [%1], %2;"
            :: "l"(out + b * MAT), "r"(smem_u32(s_mat)),
               "r"((uint32_t)HALF_BYTES) : "memory");
        asm volatile("cp.async.bulk.commit_group;" ::: "memory");
    }

    // ---- second half: rows 32..63 ----
    build_half(s_row, reinterpret_cast<float4*>(s_mat + HALF), tid, 32);
    __syncthreads();
    if (tid == 0) {
        asm volatile("fence.proxy.async.shared::cta;" ::: "memory");
        asm volatile(
            "cp.async.bulk.global.shared::cta.bulk_group [%0], [%1], %2;"
            :: "l"(out + b * MAT + HALF), "r"(smem_u32(s_mat + HALF)),
               "r"((uint32_t)HALF_BYTES) : "memory");
        asm volatile("cp.async.bulk.commit_group;" ::: "memory");
        asm volatile("cp.async.bulk.wait_group 0;" ::: "memory");
    }
}

extern "C" void kernel_launch(void* const* d_in, const int* in_sizes, int n_in,
                              void* d_out, int out_size)
{
    const float* decompFE = (const float*)d_in[0];
    float* out = (float*)d_out;

    const int batch = in_sizes[0] / NC2;   // 32768
    triangle_kernel<<<batch, THREADS>>>(decompFE, out);
}